// round 16
// baseline (speedup 1.0000x reference)
#include <cuda_runtime.h>
#include <cuda_fp16.h>
#include <cuda_bf16.h>
#include <cstdint>

#define BATCH 256
#define TM1   63
#define NI    128
#define NH    128
#define GB    2
#define NCTA  (BATCH/GB)
#define NTHR  1024

typedef unsigned int u32;

// Scratch (device globals: allocation-free rule)
__device__ float   g_P[BATCH*TM1*NI];      // P[b][t][o] = aW1_x . X[b,t] + ab1
__device__ __half2 g_Whh16[512*64];        // j-major: [j][k2], 64 u32 per row
__device__ __half2 g_aW1hc16[128*128];     // i-major: [i][k2], 128 u32 per row (k<256)

__device__ __forceinline__ float warp_sum(float v){
    v += __shfl_xor_sync(0xffffffffu, v, 16);
    v += __shfl_xor_sync(0xffffffffu, v, 8);
    v += __shfl_xor_sync(0xffffffffu, v, 4);
    v += __shfl_xor_sync(0xffffffffu, v, 2);
    v += __shfl_xor_sync(0xffffffffu, v, 1);
    return v;
}

__device__ __forceinline__ float ex2_approx(float x){
    float r;
    asm("ex2.approx.f32 %0, %1;" : "=f"(r) : "f"(x));
    return r;
}
__device__ __forceinline__ float tanh_approx(float x){
    float r;
    asm("tanh.approx.f32 %0, %1;" : "=f"(r) : "f"(x));
    return r;
}
__device__ __forceinline__ float ftanh(float x){
    float ax = fabsf(x);
    float e  = ex2_approx(ax * -2.885390082f);
    float t  = __fdividef(1.0f - e, 1.0f + e);
    return copysignf(t, x);
}
__device__ __forceinline__ float fsig(float x){
    return __fdividef(1.0f, 1.0f + ex2_approx(x * -1.442695041f));
}

#define MMA16816(d, a, b0, b1)                                              \
    asm volatile("mma.sync.aligned.m16n8k16.row.col.f32.f16.f16.f32 "       \
        "{%0,%1,%2,%3}, {%4,%5,%6,%7}, {%8,%9}, {%0,%1,%2,%3};"             \
        : "+f"((d)[0]), "+f"((d)[1]), "+f"((d)[2]), "+f"((d)[3])            \
        : "r"((a)[0]), "r"((a)[1]), "r"((a)[2]), "r"((a)[3]),               \
          "r"(b0), "r"(b1))

// ---------------- prep: weight packing ----------------
__global__ void prep_kernel(const float* __restrict__ aW1, const float* __restrict__ Whh){
    int tid = blockIdx.x*blockDim.x + threadIdx.x;
    int stride = gridDim.x*blockDim.x;
    for (int idx = tid; idx < 512*64; idx += stride){
        int j = idx >> 6, k2 = idx & 63;
        g_Whh16[idx] = __floats2half2_rn(Whh[j*128 + 2*k2], Whh[j*128 + 2*k2 + 1]);
    }
    for (int idx = tid; idx < 128*128; idx += stride){
        int i = idx >> 7, k2 = idx & 127;
        g_aW1hc16[idx] = __floats2half2_rn(aW1[i*384 + 2*k2], aW1[i*384 + 2*k2 + 1]);
    }
}

// ---------------- P precompute ----------------
__global__ void p_kernel(const float* __restrict__ X, const float* __restrict__ aW1,
                         const float* __restrict__ ab1){
    extern __shared__ char sraw[];
    float* Xs   = (float*)sraw;
    float* WT   = Xs + 8192;
    float* ab1s = WT + 128*129;
    int b = blockIdx.x, tid = threadIdx.x;
    const int PT = 256;

    for (int idx = tid; idx < 8192; idx += PT)
        Xs[idx] = (idx < TM1*NI) ? X[b*TM1*NI + idx] : 0.0f;
    for (int idx = tid; idx < 128*128; idx += PT){
        int o = idx >> 7, k = idx & 127;
        WT[k*129 + o] = aW1[o*384 + 256 + k];
    }
    if (tid < 128) ab1s[tid] = ab1[tid];
    __syncthreads();

    int o = tid & 127, half = tid >> 7;
    for (int tb = 0; tb < 8; tb++){
        int tbase = half*32 + tb*4;
        float bv = ab1s[o];
        float a0 = bv, a1 = bv, a2 = bv, a3 = bv;
        #pragma unroll 4
        for (int k = 0; k < 128; k++){
            float w = WT[k*129 + o];
            a0 = fmaf(Xs[(tbase+0)*128+k], w, a0);
            a1 = fmaf(Xs[(tbase+1)*128+k], w, a1);
            a2 = fmaf(Xs[(tbase+2)*128+k], w, a2);
            a3 = fmaf(Xs[(tbase+3)*128+k], w, a3);
        }
        if (tbase+0 < TM1) g_P[b*TM1*NI + (tbase+0)*128 + o] = a0;
        if (tbase+1 < TM1) g_P[b*TM1*NI + (tbase+1)*128 + o] = a1;
        if (tbase+2 < TM1) g_P[b*TM1*NI + (tbase+2)*128 + o] = a2;
        if (tbase+3 < TM1) g_P[b*TM1*NI + (tbase+3)*128 + o] = a3;
    }
}

// ---------------- main persistent recurrence ----------------
// Swizzle: col' = (col + 4*(row&7)) & (rowlen-1); store and load share it.
struct __align__(16) SmemMain {
    u32   WhhS[512*64];           // 131072 B, swizzled rows of 64 u32
    u32   QS[128*128];            // 65536 B, swizzled rows of 128 u32
    float qs[GB][NI];
    float ctxpart[4][GB][NI];
    float gatesH[GB][4*NH];
    float aw2[NI];
    float wfc[132];
    float wo[2*NI];
    float hc[2*NH][GB];
    __half hc16x[GB][2*NH];       // [h;c] contiguous halfs 0..255
    float scpart[8][GB][64];
    float be[GB][64];
    float XW[GB][64];
    float wih[4*NH];
    float bsum[4*NH];
    float Ys[GB][TM1+1];
    float rinv[GB];
    float yup[GB];
};

__global__ void __launch_bounds__(NTHR, 1) main_kernel(
    const float* __restrict__ X, const float* __restrict__ Y,
    const float* __restrict__ aW2,
    const float* __restrict__ Wih, const float* __restrict__ bih, const float* __restrict__ bhh,
    const float* __restrict__ Wfc, const float* __restrict__ bfc,
    const float* __restrict__ Wo,  const float* __restrict__ bo,
    float* __restrict__ out)
{
    extern __shared__ char smraw[];
    SmemMain* sm = (SmemMain*)smraw;
    int tid = threadIdx.x;
    int b0  = blockIdx.x * GB;
    int w = tid >> 5, lane = tid & 31;

    // ---- stage weights into swizzled SMEM ----
    {
        const u32* Wg = (const u32*)g_Whh16;    // [j*64 + c]
        for (int idx = tid; idx < 512*64; idx += NTHR){
            int j = idx >> 6, c = idx & 63;
            sm->WhhS[j*64 + ((c + 4*(j & 7)) & 63)] = Wg[idx];
        }
        const u32* Qg = (const u32*)g_aW1hc16;  // [i*128 + c]
        for (int idx = tid; idx < 128*128; idx += NTHR){
            int i = idx >> 7, c = idx & 127;
            sm->QS[i*128 + ((c + 4*(i & 7)) & 127)] = Qg[idx];
        }
    }
    for (int idx = tid; idx < 4*NH; idx += NTHR){
        sm->wih[idx]  = Wih[idx];
        sm->bsum[idx] = bih[idx] + bhh[idx];
    }
    for (int idx = tid; idx < GB*TM1; idx += NTHR){
        int g = idx / TM1, tt = idx % TM1;
        sm->Ys[g][tt] = Y[(b0+g)*TM1 + tt];
    }
    if (tid < NI)   sm->aw2[tid] = aW2[tid];
    if (tid < 128)  sm->wfc[tid] = Wfc[tid+1];
    if (tid == 128) sm->wfc[128] = Wfc[0];
    if (tid < 2*NI) sm->wo[tid]  = Wo[tid];
    for (int idx = tid; idx < 2*NH*GB; idx += NTHR) ((float*)sm->hc)[idx] = 0.0f;
    for (int idx = tid; idx < GB*2*NH; idx += NTHR) ((__half*)sm->hc16x)[idx] = __float2half(0.0f);
    __syncthreads();

    // ---- one-time: XW[g][tt] = wfc . X[g][tt][:] ----
    if (tid < GB*64){
        int g = tid >> 6, tt = tid & 63;
        float acc = 0.0f;
        if (tt < TM1){
            const float* Xrow = X + (b0+g)*TM1*NI + tt*NI;
            #pragma unroll 8
            for (int i = 0; i < NI; i++)
                acc = fmaf(sm->wfc[i], Xrow[i], acc);
        }
        sm->XW[g][tt] = acc;
    }

    // ---- persistent per-thread P slice (step-invariant): (g, e8, tt) -> 16 floats ----
    int sg  = tid >> 9;
    int se8 = (tid >> 6) & 7;
    int stt = tid & 63;
    int sib = se8 * 16;
    float Preg[16];
    {
        #pragma unroll
        for (int i = 0; i < 16; i++) Preg[i] = 0.0f;
        if (stt < TM1){
            const float4* Psrc = (const float4*)(g_P + (b0+sg)*TM1*NI + stt*NI + sib);
            #pragma unroll
            for (int q = 0; q < 4; q++){
                float4 v = Psrc[q];
                Preg[q*4+0] = v.x; Preg[q*4+1] = v.y;
                Preg[q*4+2] = v.z; Preg[q*4+3] = v.w;
            }
        }
    }
    __syncthreads();

    const float bfc0 = bfc[0];
    int fr = lane >> 2, fc = lane & 3;
    int rot = 4*fr;

    for (int t = 0; t < TM1; t++){
        // ======== phase 1: gates + q via HMMA, A fragments from swizzled SMEM ========
        {
            const __half* hA = sm->hc16x[(lane >> 2) & 1];
            int koff = (lane & 3) * 2;
            if (w < 8){
                // q tile: rows i0..i0+15, 16 k-tiles over contiguous [h;c]
                int i0 = w*16;
                const u32* Q0 = &sm->QS[(i0 + fr)*128];
                const u32* Q1 = &sm->QS[(i0 + 8 + fr)*128];
                float d[4] = {0.f,0.f,0.f,0.f};
                #pragma unroll
                for (int kt = 0; kt < 16; kt++){
                    int c0 = (kt*8 + fc + rot) & 127;
                    int c1 = (kt*8 + fc + 4 + rot) & 127;
                    u32 a[4];
                    a[0] = Q0[c0];
                    a[1] = Q1[c0];
                    a[2] = Q0[c1];
                    a[3] = Q1[c1];
                    u32 bb0 = *(const u32*)&hA[kt*16 + koff];
                    u32 bb1 = *(const u32*)&hA[kt*16 + koff + 8];
                    MMA16816(d, a, bb0, bb1);
                }
                if ((lane & 3) == 0){
                    sm->qs[0][i0 + fr]     = d[0];
                    sm->qs[1][i0 + fr]     = d[1];
                    sm->qs[0][i0 + 8 + fr] = d[2];
                    sm->qs[1][i0 + 8 + fr] = d[3];
                }
            } else {
                // gates tiles: warps 8..31 -> tile w-8; warps 8..15 also tile w+16
                int ntile = (w < 16) ? 2 : 1;
                int tiles[2] = { (w - 8), (w + 16) };
                for (int ti = 0; ti < ntile; ti++){
                    int j0 = tiles[ti]*16;
                    const u32* W0 = &sm->WhhS[(j0 + fr)*64];
                    const u32* W1 = &sm->WhhS[(j0 + 8 + fr)*64];
                    float d[4] = {0.f,0.f,0.f,0.f};
                    #pragma unroll
                    for (int kt = 0; kt < 8; kt++){
                        int c0 = (kt*8 + fc + rot) & 63;
                        int c1 = (kt*8 + fc + 4 + rot) & 63;
                        u32 a[4];
                        a[0] = W0[c0];
                        a[1] = W1[c0];
                        a[2] = W0[c1];
                        a[3] = W1[c1];
                        u32 bb0 = *(const u32*)&hA[kt*16 + koff];
                        u32 bb1 = *(const u32*)&hA[kt*16 + koff + 8];
                        MMA16816(d, a, bb0, bb1);
                    }
                    if ((lane & 3) == 0){
                        sm->gatesH[0][j0 + fr]     = d[0];
                        sm->gatesH[1][j0 + fr]     = d[1];
                        sm->gatesH[0][j0 + 8 + fr] = d[2];
                        sm->gatesH[1][j0 + 8 + fr] = d[3];
                    }
                }
            }
        }
        __syncthreads();
        // ======== phase 2: scores (thread = (g, e8, tt), 16-wide dot; P in regs) ========
        {
            float acc = 0.0f;
            if (stt < TM1){
                const float* qrow = &sm->qs[sg][sib];
                const float* arow = &sm->aw2[sib];
                #pragma unroll
                for (int i = 0; i < 16; i++)
                    acc = fmaf(arow[i], tanh_approx(Preg[i] + qrow[i]), acc);
            }
            sm->scpart[se8][sg][stt] = acc;
        }
        __syncthreads();
        // ======== phase 3: softmax (no max-sub; scores bounded) + y_update ========
        if (w == 0 || w == 16){
            int g = w >> 4;
            float s0 = 0.f, s1 = 0.f;
            #pragma unroll
            for (int p = 0; p < 8; p++){
                s0 += sm->scpart[p][g][lane];
                if (lane < 31) s1 += sm->scpart[p][g][32+lane];
            }
            float e0 = ex2_approx(s0 * 1.442695041f);
            float e1 = (lane < 31) ? ex2_approx(s1 * 1.442695041f) : 0.0f;
            float sv = e0 + e1;
            float dv = e0 * sm->XW[g][lane] + e1 * sm->XW[g][32 + lane];
            #pragma unroll
            for (int off = 16; off > 0; off >>= 1){
                sv += __shfl_xor_sync(0xffffffffu, sv, off);
                dv += __shfl_xor_sync(0xffffffffu, dv, off);
            }
            if (t == TM1-1){
                sm->be[g][lane] = e0;
                if (lane < 31) sm->be[g][32+lane] = e1;
            }
            if (lane == 0){
                float ri = __fdividef(1.0f, sv);
                sm->rinv[g] = ri;
                float yt = sm->Ys[g][t];
                sm->yup[g] = fmaf(dv, ri, fmaf(sm->wfc[128], yt, bfc0));
            }
        }
        __syncthreads();
        // ======== phase 4: LSTM cell (accurate activations) ========
        if (tid < 256){
            int g = tid >> 7, i = tid & 127;
            float yu = sm->yup[g];
            float gi = sm->gatesH[g][i]        + yu*sm->wih[i]        + sm->bsum[i];
            float gf = sm->gatesH[g][NH+i]     + yu*sm->wih[NH+i]     + sm->bsum[NH+i];
            float gg = sm->gatesH[g][2*NH+i]   + yu*sm->wih[2*NH+i]   + sm->bsum[2*NH+i];
            float go = sm->gatesH[g][3*NH+i]   + yu*sm->wih[3*NH+i]   + sm->bsum[3*NH+i];
            float co = sm->hc[NH+i][g];
            float cn = fsig(gf)*co + fsig(gi)*ftanh(gg);
            float hn = fsig(go)*ftanh(cn);
            sm->hc[i][g]       = hn;
            sm->hc[NH+i][g]    = cn;
            sm->hc16x[g][i]    = __float2half(hn);
            sm->hc16x[g][NH+i] = __float2half(cn);
        }
        __syncthreads();
    }

    // ---- final context from last step's be/rinv (X from global, 4-way t-split) ----
    {
        int g = tid >> 9, q4 = (tid >> 7) & 3, i = tid & 127;
        int t0 = q4*16;
        int t1 = (q4 == 3) ? TM1 : (t0 + 16);
        const float* Xg = X + (b0+g)*TM1*NI;
        float acc = 0.0f;
        for (int tt = t0; tt < t1; tt++)
            acc = fmaf(sm->be[g][tt], Xg[tt*NI + i], acc);
        sm->ctxpart[q4][g][i] = acc;
    }
    __syncthreads();

    // ---- output: y[b] = bo + Wo[0:128].h + Wo[128:256].ctx  (warps 0 and 16) ----
    if (w == 0 || w == 16){
        int g = w >> 4;
        float ri = sm->rinv[g];
        float acc = 0.0f;
        #pragma unroll
        for (int r = 0; r < 4; r++){
            int i = lane*4 + r;
            float ctx = (sm->ctxpart[0][g][i] + sm->ctxpart[1][g][i]
                       + sm->ctxpart[2][g][i] + sm->ctxpart[3][g][i]) * ri;
            acc += sm->wo[i]*sm->hc[i][g] + sm->wo[NI+i]*ctx;
        }
        acc = warp_sum(acc);
        if (lane == 0) out[b0 + g] = acc + bo[0];
    }
}

extern "C" void kernel_launch(void* const* d_in, const int* in_sizes, int n_in,
                              void* d_out, int out_size) {
    const float* X   = (const float*)d_in[0];
    const float* Y   = (const float*)d_in[1];
    const float* aW1 = (const float*)d_in[2];
    const float* ab1 = (const float*)d_in[3];
    const float* aW2 = (const float*)d_in[4];
    // d_in[5] = ab2: constant softmax shift, mathematically irrelevant
    const float* Wih = (const float*)d_in[6];
    const float* Whh = (const float*)d_in[7];
    const float* bih = (const float*)d_in[8];
    const float* bhh = (const float*)d_in[9];
    const float* Wfc = (const float*)d_in[10];
    const float* bfc = (const float*)d_in[11];
    const float* Wo  = (const float*)d_in[12];
    const float* bo  = (const float*)d_in[13];
    float* out = (float*)d_out;

    size_t p_smem = (size_t)(8192 + 128*129 + 128) * sizeof(float);
    size_t m_smem = sizeof(SmemMain);
    cudaFuncSetAttribute(p_kernel,    cudaFuncAttributeMaxDynamicSharedMemorySize, (int)p_smem);
    cudaFuncSetAttribute(main_kernel, cudaFuncAttributeMaxDynamicSharedMemorySize, (int)m_smem);

    prep_kernel<<<64, 256>>>(aW1, Whh);
    p_kernel<<<BATCH, 256, p_smem>>>(X, aW1, ab1);
    main_kernel<<<NCTA, NTHR, m_smem>>>(X, Y, aW2, Wih, bih, bhh, Wfc, bfc, Wo, bo, out);
}

// round 17
// speedup vs baseline: 1.3884x; 1.3884x over previous
#include <cuda_runtime.h>
#include <cuda_fp16.h>
#include <cuda_bf16.h>
#include <cstdint>

#define BATCH 256
#define TM1   63
#define NI    128
#define NH    128
#define GB    2
#define NCTA  (BATCH/GB)
#define NTHR  512
#define PPITCH 129

typedef unsigned int u32;

// Scratch (device globals: allocation-free rule)
__device__ float   g_P[BATCH*TM1*NI];      // P[b][t][o] = aW1_x . X[b,t] + ab1
__device__ __half2 g_Whh16[512*64];        // j-major: [j][k2]
__device__ __half2 g_aW1hc16[128*128];     // i-major: [i][k2], k<256

__device__ __forceinline__ float warp_sum(float v){
    v += __shfl_xor_sync(0xffffffffu, v, 16);
    v += __shfl_xor_sync(0xffffffffu, v, 8);
    v += __shfl_xor_sync(0xffffffffu, v, 4);
    v += __shfl_xor_sync(0xffffffffu, v, 2);
    v += __shfl_xor_sync(0xffffffffu, v, 1);
    return v;
}

__device__ __forceinline__ float ex2_approx(float x){
    float r;
    asm("ex2.approx.f32 %0, %1;" : "=f"(r) : "f"(x));
    return r;
}
__device__ __forceinline__ float tanh_approx(float x){
    float r;
    asm("tanh.approx.f32 %0, %1;" : "=f"(r) : "f"(x));
    return r;
}
__device__ __forceinline__ float ftanh(float x){
    float ax = fabsf(x);
    float e  = ex2_approx(ax * -2.885390082f);
    float t  = __fdividef(1.0f - e, 1.0f + e);
    return copysignf(t, x);
}
__device__ __forceinline__ float fsig(float x){
    return __fdividef(1.0f, 1.0f + ex2_approx(x * -1.442695041f));
}

#define MMA16816(d, a, b0, b1)                                              \
    asm volatile("mma.sync.aligned.m16n8k16.row.col.f32.f16.f16.f32 "       \
        "{%0,%1,%2,%3}, {%4,%5,%6,%7}, {%8,%9}, {%0,%1,%2,%3};"             \
        : "+f"((d)[0]), "+f"((d)[1]), "+f"((d)[2]), "+f"((d)[3])            \
        : "r"((a)[0]), "r"((a)[1]), "r"((a)[2]), "r"((a)[3]),               \
          "r"(b0), "r"(b1))

// ---------------- prep: weight packing ----------------
__global__ void prep_kernel(const float* __restrict__ aW1, const float* __restrict__ Whh){
    int tid = blockIdx.x*blockDim.x + threadIdx.x;
    int stride = gridDim.x*blockDim.x;
    for (int idx = tid; idx < 512*64; idx += stride){
        int j = idx >> 6, k2 = idx & 63;
        g_Whh16[idx] = __floats2half2_rn(Whh[j*128 + 2*k2], Whh[j*128 + 2*k2 + 1]);
    }
    for (int idx = tid; idx < 128*128; idx += stride){
        int i = idx >> 7, k2 = idx & 127;
        g_aW1hc16[idx] = __floats2half2_rn(aW1[i*384 + 2*k2], aW1[i*384 + 2*k2 + 1]);
    }
}

// ---------------- P precompute ----------------
__global__ void p_kernel(const float* __restrict__ X, const float* __restrict__ aW1,
                         const float* __restrict__ ab1){
    extern __shared__ char sraw[];
    float* Xs   = (float*)sraw;
    float* WT   = Xs + 8192;
    float* ab1s = WT + 128*129;
    int b = blockIdx.x, tid = threadIdx.x;
    const int PT = 256;

    for (int idx = tid; idx < 8192; idx += PT)
        Xs[idx] = (idx < TM1*NI) ? X[b*TM1*NI + idx] : 0.0f;
    for (int idx = tid; idx < 128*128; idx += PT){
        int o = idx >> 7, k = idx & 127;
        WT[k*129 + o] = aW1[o*384 + 256 + k];
    }
    if (tid < 128) ab1s[tid] = ab1[tid];
    __syncthreads();

    int o = tid & 127, half = tid >> 7;
    for (int tb = 0; tb < 8; tb++){
        int tbase = half*32 + tb*4;
        float bv = ab1s[o];
        float a0 = bv, a1 = bv, a2 = bv, a3 = bv;
        #pragma unroll 4
        for (int k = 0; k < 128; k++){
            float w = WT[k*129 + o];
            a0 = fmaf(Xs[(tbase+0)*128+k], w, a0);
            a1 = fmaf(Xs[(tbase+1)*128+k], w, a1);
            a2 = fmaf(Xs[(tbase+2)*128+k], w, a2);
            a3 = fmaf(Xs[(tbase+3)*128+k], w, a3);
        }
        if (tbase+0 < TM1) g_P[b*TM1*NI + (tbase+0)*128 + o] = a0;
        if (tbase+1 < TM1) g_P[b*TM1*NI + (tbase+1)*128 + o] = a1;
        if (tbase+2 < TM1) g_P[b*TM1*NI + (tbase+2)*128 + o] = a2;
        if (tbase+3 < TM1) g_P[b*TM1*NI + (tbase+3)*128 + o] = a3;
    }
}

// ---------------- main persistent recurrence ----------------
struct __align__(16) SmemMain {
    float Ps[GB][TM1][PPITCH];    // 65016 B
    float _pad0[2];
    float qs[GB][NI];
    float ctxpart[2][GB][NI];
    float gatesH[GB][4*NH];
    float aw2[NI];
    float wfc[132];               // [0..127]=Wfc[1..128], [128]=Wfc[0]
    float wo[2*NI];
    float hc[2*NH][GB];           // fp32 [k][g]
    __half hc16x[GB][2*NH];       // fp16 [h;c]: h@[0..127], c@[128..255]
    float scpart[4][GB][64];
    float be[GB][64];
    float XW[GB][64];
    float wih[4*NH];
    float bsum[4*NH];
    float Ys[GB][TM1+1];
    float rinv[GB];
};

__global__ void __launch_bounds__(NTHR, 1) main_kernel(
    const float* __restrict__ X, const float* __restrict__ Y,
    const float* __restrict__ aW2,
    const float* __restrict__ Wih, const float* __restrict__ bih, const float* __restrict__ bhh,
    const float* __restrict__ Wfc, const float* __restrict__ bfc,
    const float* __restrict__ Wo,  const float* __restrict__ bo,
    float* __restrict__ out)
{
    extern __shared__ char smraw[];
    SmemMain* sm = (SmemMain*)smraw;
    int tid = threadIdx.x;
    int b0  = blockIdx.x * GB;
    int w = tid >> 5, lane = tid & 31;

    // ---- persistent A fragments (96 regs/thread, as validated in R14) ----
    u32 Af[3][8][4];
    {
        const u32* Wg = (const u32*)g_Whh16;    // [j*64 + k2]
        const u32* Qg = (const u32*)g_aW1hc16;  // [i*128 + k2]
        int r = lane >> 2, cq = lane & 3;
        if (w < 8){
            #pragma unroll
            for (int m = 0; m < 3; m++){
                int j0 = w*48 + m*16;
                #pragma unroll
                for (int kt = 0; kt < 8; kt++){
                    int base = kt*8 + cq;
                    Af[m][kt][0] = Wg[(j0 + r)*64     + base];
                    Af[m][kt][1] = Wg[(j0 + 8 + r)*64 + base];
                    Af[m][kt][2] = Wg[(j0 + r)*64     + base + 4];
                    Af[m][kt][3] = Wg[(j0 + 8 + r)*64 + base + 4];
                }
            }
        } else {
            int j0 = 384 + (w-8)*16;
            int i0 = (w-8)*16;
            #pragma unroll
            for (int kt = 0; kt < 8; kt++){
                int base = kt*8 + cq;
                Af[0][kt][0] = Wg[(j0 + r)*64     + base];
                Af[0][kt][1] = Wg[(j0 + 8 + r)*64 + base];
                Af[0][kt][2] = Wg[(j0 + r)*64     + base + 4];
                Af[0][kt][3] = Wg[(j0 + 8 + r)*64 + base + 4];
                Af[1][kt][0] = Qg[(i0 + r)*128     + base];
                Af[1][kt][1] = Qg[(i0 + 8 + r)*128 + base];
                Af[1][kt][2] = Qg[(i0 + r)*128     + base + 4];
                Af[1][kt][3] = Qg[(i0 + 8 + r)*128 + base + 4];
                int base2 = 64 + kt*8 + cq;
                Af[2][kt][0] = Qg[(i0 + r)*128     + base2];
                Af[2][kt][1] = Qg[(i0 + 8 + r)*128 + base2];
                Af[2][kt][2] = Qg[(i0 + r)*128     + base2 + 4];
                Af[2][kt][3] = Qg[(i0 + 8 + r)*128 + base2 + 4];
            }
        }
    }

    // ---- stage: Ps, small weights ----
    for (int idx = tid; idx < GB*TM1*NI; idx += NTHR){
        int g = idx / (TM1*NI), r = idx % (TM1*NI);
        int tt = r >> 7, i = r & 127;
        sm->Ps[g][tt][i] = g_P[b0*TM1*NI + idx];
    }
    for (int idx = tid; idx < 4*NH; idx += NTHR){
        sm->wih[idx]  = Wih[idx];
        sm->bsum[idx] = bih[idx] + bhh[idx];
    }
    for (int idx = tid; idx < GB*TM1; idx += NTHR){
        int g = idx / TM1, tt = idx % TM1;
        sm->Ys[g][tt] = Y[(b0+g)*TM1 + tt];
    }
    if (tid < NI)   sm->aw2[tid] = aW2[tid];
    if (tid < 128)  sm->wfc[tid] = Wfc[tid+1];
    if (tid == 128) sm->wfc[128] = Wfc[0];
    if (tid < 2*NI) sm->wo[tid]  = Wo[tid];
    for (int idx = tid; idx < 2*NH*GB; idx += NTHR) ((float*)sm->hc)[idx] = 0.0f;
    for (int idx = tid; idx < GB*2*NH; idx += NTHR) ((__half*)sm->hc16x)[idx] = __float2half(0.0f);
    __syncthreads();

    // ---- one-time: XW[g][tt] = wfc . X[g][tt][:]  (X from global) ----
    if (tid < GB*64){
        int g = tid >> 6, tt = tid & 63;
        float acc = 0.0f;
        if (tt < TM1){
            const float* Xrow = X + (b0+g)*TM1*NI + tt*NI;
            #pragma unroll 8
            for (int i = 0; i < NI; i++)
                acc = fmaf(sm->wfc[i], Xrow[i], acc);
        }
        sm->XW[g][tt] = acc;
    }
    __syncthreads();

    const float bfc0 = bfc[0];

    for (int t = 0; t < TM1; t++){
        // ======== phase 1: gates + q via HMMA (A in regs, B = hc16x) ========
        {
            const __half* hA = sm->hc16x[(lane >> 2) & 1];
            int koff = (lane & 3) * 2;
            if (w < 8){
                float d0[4] = {0.f,0.f,0.f,0.f};
                float d1[4] = {0.f,0.f,0.f,0.f};
                float d2[4] = {0.f,0.f,0.f,0.f};
                #pragma unroll
                for (int kt = 0; kt < 8; kt++){
                    u32 bb0 = *(const u32*)&hA[kt*16 + koff];
                    u32 bb1 = *(const u32*)&hA[kt*16 + koff + 8];
                    MMA16816(d0, Af[0][kt], bb0, bb1);
                    MMA16816(d1, Af[1][kt], bb0, bb1);
                    MMA16816(d2, Af[2][kt], bb0, bb1);
                }
                if ((lane & 3) == 0){
                    int rr = lane >> 2;
                    int j0 = w*48;
                    sm->gatesH[0][j0 + rr]       = d0[0];
                    sm->gatesH[1][j0 + rr]       = d0[1];
                    sm->gatesH[0][j0 + 8 + rr]   = d0[2];
                    sm->gatesH[1][j0 + 8 + rr]   = d0[3];
                    sm->gatesH[0][j0 + 16 + rr]  = d1[0];
                    sm->gatesH[1][j0 + 16 + rr]  = d1[1];
                    sm->gatesH[0][j0 + 24 + rr]  = d1[2];
                    sm->gatesH[1][j0 + 24 + rr]  = d1[3];
                    sm->gatesH[0][j0 + 32 + rr]  = d2[0];
                    sm->gatesH[1][j0 + 32 + rr]  = d2[1];
                    sm->gatesH[0][j0 + 40 + rr]  = d2[2];
                    sm->gatesH[1][j0 + 40 + rr]  = d2[3];
                }
            } else {
                float dg[4]  = {0.f,0.f,0.f,0.f};
                float dqa[4] = {0.f,0.f,0.f,0.f};
                float dqb[4] = {0.f,0.f,0.f,0.f};
                #pragma unroll
                for (int kt = 0; kt < 8; kt++){
                    u32 bb0 = *(const u32*)&hA[kt*16 + koff];
                    u32 bb1 = *(const u32*)&hA[kt*16 + koff + 8];
                    MMA16816(dg,  Af[0][kt], bb0, bb1);
                    MMA16816(dqa, Af[1][kt], bb0, bb1);
                    // c part of [h;c] at hA[128 + k] — independent accumulator chain
                    u32 cc0 = *(const u32*)&hA[128 + kt*16 + koff];
                    u32 cc1 = *(const u32*)&hA[128 + kt*16 + koff + 8];
                    MMA16816(dqb, Af[2][kt], cc0, cc1);
                }
                if ((lane & 3) == 0){
                    int rr = lane >> 2;
                    int j0 = 384 + (w-8)*16;
                    int i0 = (w-8)*16;
                    sm->gatesH[0][j0 + rr]      = dg[0];
                    sm->gatesH[1][j0 + rr]      = dg[1];
                    sm->gatesH[0][j0 + 8 + rr]  = dg[2];
                    sm->gatesH[1][j0 + 8 + rr]  = dg[3];
                    sm->qs[0][i0 + rr]          = dqa[0] + dqb[0];
                    sm->qs[1][i0 + rr]          = dqa[1] + dqb[1];
                    sm->qs[0][i0 + 8 + rr]      = dqa[2] + dqb[2];
                    sm->qs[1][i0 + 8 + rr]      = dqa[3] + dqb[3];
                }
            }
        }
        __syncthreads();
        // ======== phase 2: scores (thread = (g, quarter, tt), 32-wide dot) ========
        {
            int g   = tid >> 8;
            int qtr = (tid >> 6) & 3;
            int tt  = tid & 63;
            int ibase = qtr * 32;
            float acc = 0.0f;
            if (tt < TM1){
                const float* Prow = &sm->Ps[g][tt][ibase];
                const float* qrow = &sm->qs[g][ibase];
                const float* arow = &sm->aw2[ibase];
                #pragma unroll 8
                for (int i = 0; i < 32; i++)
                    acc = fmaf(arow[i], tanh_approx(Prow[i] + qrow[i]), acc);
            }
            sm->scpart[qtr][g][tt] = acc;
        }
        __syncthreads();
        // ======== phase 3+4 merged: per-warp softmax + LSTM (warps 0-7) ========
        if (tid < 256){
            int g = tid >> 7, i = tid & 127;
            // redundant softmax per warp (all lanes end with yup in-register)
            float s0 = sm->scpart[0][g][lane] + sm->scpart[1][g][lane]
                     + sm->scpart[2][g][lane] + sm->scpart[3][g][lane];
            float e0 = ex2_approx(s0 * 1.442695041f);
            float e1 = 0.0f;
            if (lane < 31){
                float s1 = sm->scpart[0][g][32+lane] + sm->scpart[1][g][32+lane]
                         + sm->scpart[2][g][32+lane] + sm->scpart[3][g][32+lane];
                e1 = ex2_approx(s1 * 1.442695041f);
            }
            float sv = e0 + e1;
            float dv = e0 * sm->XW[g][lane] + e1 * sm->XW[g][32 + lane];
            #pragma unroll
            for (int off = 16; off > 0; off >>= 1){
                sv += __shfl_xor_sync(0xffffffffu, sv, off);
                dv += __shfl_xor_sync(0xffffffffu, dv, off);
            }
            float ri = __fdividef(1.0f, sv);
            float yu = fmaf(dv, ri, fmaf(sm->wfc[128], sm->Ys[g][t], bfc0));
            if (t == TM1-1 && (w == 0 || w == 4)){
                sm->be[g][lane] = e0;
                if (lane < 31) sm->be[g][32+lane] = e1;
                if (lane == 0) sm->rinv[g] = ri;
            }
            // LSTM cell
            float gi = sm->gatesH[g][i]        + yu*sm->wih[i]        + sm->bsum[i];
            float gf = sm->gatesH[g][NH+i]     + yu*sm->wih[NH+i]     + sm->bsum[NH+i];
            float gg = sm->gatesH[g][2*NH+i]   + yu*sm->wih[2*NH+i]   + sm->bsum[2*NH+i];
            float go = sm->gatesH[g][3*NH+i]   + yu*sm->wih[3*NH+i]   + sm->bsum[3*NH+i];
            float co = sm->hc[NH+i][g];
            float cn = fsig(gf)*co + fsig(gi)*ftanh(gg);
            float hn = fsig(go)*ftanh(cn);
            sm->hc[i][g]       = hn;
            sm->hc[NH+i][g]    = cn;
            sm->hc16x[g][i]    = __float2half(hn);
            sm->hc16x[g][NH+i] = __float2half(cn);
        }
        __syncthreads();
    }

    // ---- final context from last step's be/rinv (X from global) ----
    {
        int g = tid >> 8, half = (tid >> 7) & 1, i = tid & 127;
        int t0 = half ? 32 : 0;
        int t1 = half ? TM1 : 32;
        const float* Xg = X + (b0+g)*TM1*NI;
        float acc = 0.0f;
        for (int tt = t0; tt < t1; tt++)
            acc = fmaf(sm->be[g][tt], Xg[tt*NI + i], acc);
        sm->ctxpart[half][g][i] = acc;
    }
    __syncthreads();

    // ---- output: y[b] = bo + Wo[0:128].h + Wo[128:256].ctx  (warps 0 and 8) ----
    if (w == 0 || w == 8){
        int g = w >> 3;
        float ri = sm->rinv[g];
        float acc = 0.0f;
        #pragma unroll
        for (int r = 0; r < 4; r++){
            int i = lane*4 + r;
            float ctx = (sm->ctxpart[0][g][i] + sm->ctxpart[1][g][i]) * ri;
            acc += sm->wo[i]*sm->hc[i][g] + sm->wo[NI+i]*ctx;
        }
        acc = warp_sum(acc);
        if (lane == 0) out[b0 + g] = acc + bo[0];
    }
}

extern "C" void kernel_launch(void* const* d_in, const int* in_sizes, int n_in,
                              void* d_out, int out_size) {
    const float* X   = (const float*)d_in[0];
    const float* Y   = (const float*)d_in[1];
    const float* aW1 = (const float*)d_in[2];
    const float* ab1 = (const float*)d_in[3];
    const float* aW2 = (const float*)d_in[4];
    // d_in[5] = ab2: constant softmax shift, mathematically irrelevant
    const float* Wih = (const float*)d_in[6];
    const float* Whh = (const float*)d_in[7];
    const float* bih = (const float*)d_in[8];
    const float* bhh = (const float*)d_in[9];
    const float* Wfc = (const float*)d_in[10];
    const float* bfc = (const float*)d_in[11];
    const float* Wo  = (const float*)d_in[12];
    const float* bo  = (const float*)d_in[13];
    float* out = (float*)d_out;

    size_t p_smem = (size_t)(8192 + 128*129 + 128) * sizeof(float);
    size_t m_smem = sizeof(SmemMain);
    cudaFuncSetAttribute(p_kernel,    cudaFuncAttributeMaxDynamicSharedMemorySize, (int)p_smem);
    cudaFuncSetAttribute(main_kernel, cudaFuncAttributeMaxDynamicSharedMemorySize, (int)m_smem);

    prep_kernel<<<64, 256>>>(aW1, Whh);
    p_kernel<<<BATCH, 256, p_smem>>>(X, aW1, ab1);
    main_kernel<<<NCTA, NTHR, m_smem>>>(X, Y, aW2, Wih, bih, bhh, Wfc, bfc, Wo, bo, out);
}